// round 16
// baseline (speedup 1.0000x reference)
#include <cuda_runtime.h>
#include <cuda_bf16.h>
#include <cuda_fp16.h>
#include <math.h>
#include <stdint.h>

#define BATCH 2
#define SEQ   2048
#define DIMM  1024
#define HEADS 16
#define DHD   64
#define INNER_ (HEADS*DHD)      // 1024
#define ROWS  (BATCH*SEQ)       // 4096
#define KDIM  1024
#define LOG2E 1.4426950408889634f

// ---------------- scratch (no cudaMalloc allowed) ----------------
__device__ __align__(256) __half g_qf [ROWS*INNER_];
__device__ __align__(256) __half g_kf [BATCH*SEQ*DHD];
__device__ __align__(256) __half g_vtf[BATCH*DHD*SEQ];
__device__ __align__(256) __half g_aof[ROWS*INNER_];
__device__ __align__(256) __half g_xf [ROWS*DIMM];
__device__ __align__(256) __half g_wcf[(INNER_+2*DHD)*DIMM];   // [Wq^T ; Wkv^T] fp16
__device__ __align__(256) __half g_wof[DIMM*INNER_];           // Wout^T fp16

// ---------------- helpers ----------------
__device__ __forceinline__ uint32_t s2u(const void* p) {
    uint32_t a;
    asm("{ .reg .u64 t; cvta.to.shared.u64 t, %1; cvt.u32.u64 %0, t; }"
        : "=r"(a) : "l"(p));
    return a;
}
__device__ __forceinline__ void cp16(uint32_t dst, const void* src) {
    asm volatile("cp.async.cg.shared.global [%0], [%1], 16;" :: "r"(dst), "l"(src));
}
__device__ __forceinline__ void cp_commit() { asm volatile("cp.async.commit_group;" ::: "memory"); }

__device__ __forceinline__ void mma16816h(float c[4], const uint32_t a[4], const uint32_t b[2]) {
    asm volatile("mma.sync.aligned.m16n8k16.row.col.f32.f16.f16.f32 "
        "{%0,%1,%2,%3}, {%4,%5,%6,%7}, {%8,%9}, {%0,%1,%2,%3};"
        : "+f"(c[0]), "+f"(c[1]), "+f"(c[2]), "+f"(c[3])
        : "r"(a[0]), "r"(a[1]), "r"(a[2]), "r"(a[3]), "r"(b[0]), "r"(b[1]));
}

// ldmatrix x4
__device__ __forceinline__ void ldsm_x4(uint32_t r[4], uint32_t saddr) {
    asm volatile("ldmatrix.sync.aligned.m8n8.x4.shared.b16 {%0,%1,%2,%3}, [%4];"
        : "=r"(r[0]), "=r"(r[1]), "=r"(r[2]), "=r"(r[3]) : "r"(saddr));
}

// pack two floats -> fp16x2 (first arg = low half)
__device__ __forceinline__ uint32_t pack_f16x2(float lo, float hi) {
    uint32_t r;
    asm("cvt.rn.f16x2.f32 %0, %1, %2;" : "=r"(r) : "f"(hi), "f"(lo));
    return r;
}
// exp2 on packed fp16x2
__device__ __forceinline__ uint32_t ex2_f16x2(uint32_t a) {
    uint32_t r;
    asm("ex2.approx.f16x2 %0, %1;" : "=r"(r) : "r"(a));
    return r;
}

// ---------------------------------------------------------------------------
// Prep kernels
// ---------------------------------------------------------------------------
__global__ __launch_bounds__(256) void convert_f16_kernel(
    const float* __restrict__ A, __half* __restrict__ F, int n4)
{
    int i = blockIdx.x * blockDim.x + threadIdx.x;
    if (i >= n4) return;
    float4 a = ((const float4*)A)[i];
    ((uint32_t*)F)[2*i]   = pack_f16x2(a.x, a.y);
    ((uint32_t*)F)[2*i+1] = pack_f16x2(a.z, a.w);
}

__global__ __launch_bounds__(256) void transpose_f16_kernel(
    const float* __restrict__ W, __half* __restrict__ T,
    int K, int N, float scale)
{
    __shared__ float tile[32][33];
    const int tx = threadIdx.x, ty = threadIdx.y;
    const int n0 = blockIdx.x * 32, k0 = blockIdx.y * 32;
    #pragma unroll
    for (int i = 0; i < 4; i++)
        tile[ty + 8*i][tx] = W[(size_t)(k0 + ty + 8*i) * N + n0 + tx];
    __syncthreads();
    #pragma unroll
    for (int i = 0; i < 4; i++) {
        float a = tile[tx][ty + 8*i] * scale;
        T[(size_t)(n0 + ty + 8*i) * K + k0 + tx] = __float2half_rn(a);
    }
}

__global__ __launch_bounds__(256) void transpose_wc_kernel(
    const float* __restrict__ Wq, const float* __restrict__ Wkv,
    __half* __restrict__ T)
{
    __shared__ float tile[32][33];
    const int tx = threadIdx.x, ty = threadIdx.y;
    const int n0 = blockIdx.x * 32, k0 = blockIdx.y * 32;
    const bool isq = (n0 < INNER_);
    const float* W = isq ? Wq : Wkv;
    const int N = isq ? INNER_ : 2*DHD;
    const int cb = isq ? n0 : n0 - INNER_;
    const float scale = isq ? 0.125f * LOG2E : 1.0f;
    #pragma unroll
    for (int i = 0; i < 4; i++)
        tile[ty + 8*i][tx] = W[(size_t)(k0 + ty + 8*i) * N + cb + tx];
    __syncthreads();
    #pragma unroll
    for (int i = 0; i < 4; i++) {
        float a = tile[tx][ty + 8*i] * scale;
        T[(size_t)(n0 + ty + 8*i) * KDIM + k0 + tx] = __float2half_rn(a);
    }
}

// ---------------------------------------------------------------------------
// HMMA GEMM fp16: C = A[M,K] @ B^T, fp16 [.][K]. CTA 128x128, BK=64,
// CORRECT 2-buffer double-buffer (trailing sync protects buffer reuse).
// MODE 0: fp32 C + bias.
// MODE 1: bn<8 -> fp16 q; bn==8 -> K fp16 (cols 0..63) + V^T fp16 (cols 64..127).
// ---------------------------------------------------------------------------
#define GBK 64
#define GNSTG (KDIM/GBK)            // 16
#define GSTRIDE 72                  // elements; 144 bytes/row
#define GMATB (128*GSTRIDE*2)       // 18432 bytes per matrix
#define GSTGB (2*GMATB)             // 36864 per stage
#define GEMM_SMEM (2*GSTGB)         // 73728 (2 buffers)

template<int MODE>
__global__ __launch_bounds__(256, 2) void gemm_mma(
    const __half* __restrict__ Af, const __half* __restrict__ Bf,
    float* __restrict__ C, const float* __restrict__ bias, int Ncols,
    __half* __restrict__ CF, __half* __restrict__ KF, __half* __restrict__ VTF)
{
    extern __shared__ __align__(16) char smem[];
    const uint32_t sbuf = s2u(smem);
    const int tid = threadIdx.x, wid = tid >> 5, lane = tid & 31;
    const int l4 = lane >> 2, c2 = (lane & 3) * 2;
    const int wm = wid & 3, wn = wid >> 2;
    const int bn = blockIdx.x, bm = blockIdx.y;

    const uint32_t ltermB = ((lane & 7) + ((lane >> 4) << 3)) * 144
                          + (((lane >> 3) & 1) << 4);
    const uint32_t ltermA = ((lane & 7) + (((lane >> 3) & 1) << 3)) * 144
                          + (((lane >> 4) & 1) << 4);

    const __half* pA = Af + (size_t)(bm*128)*KDIM;
    const __half* pB = Bf + (size_t)(bn*128)*KDIM;

    float acc[2][8][4];
    #pragma unroll
    for (int i = 0; i < 2; i++)
        #pragma unroll
        for (int j = 0; j < 8; j++)
            #pragma unroll
            for (int e = 0; e < 4; e++) acc[i][j][e] = 0.f;

    // stage loader: per matrix 128 rows x 8 chunks of 16B = 1024; 4 per thread.
    #define G_LOAD(S) do { \
        const int _k0 = (S) * GBK; \
        const uint32_t stb = sbuf + (uint32_t)((S) & 1) * GSTGB; \
        _Pragma("unroll") \
        for (int q = 0; q < 4; q++) { \
            const int c = tid*4 + q; \
            const int r = c >> 3, cc = c & 7; \
            const uint32_t so = (uint32_t)(r*144 + cc*16); \
            cp16(stb         + so, pA + (size_t)r*KDIM + _k0 + cc*8); \
            cp16(stb + GMATB + so, pB + (size_t)r*KDIM + _k0 + cc*8); \
        } \
    } while (0)

    G_LOAD(0); cp_commit();

    for (int s = 0; s < GNSTG; s++) {
        if (s + 1 < GNSTG) {
            G_LOAD(s + 1); cp_commit();
            asm volatile("cp.async.wait_group 1;" ::: "memory");
        } else {
            asm volatile("cp.async.wait_group 0;" ::: "memory");
        }
        __syncthreads();

        const uint32_t stb = sbuf + (uint32_t)(s & 1) * GSTGB;
        const uint32_t aBase = stb         + (wm*32)*144 + ltermA;
        const uint32_t bBase = stb + GMATB + (wn*64)*144 + ltermB;

        #pragma unroll
        for (int k16 = 0; k16 < 4; k16++) {
            const uint32_t kc2 = (uint32_t)k16 * 32;
            uint32_t ah[2][4], bb[4][4];
            #pragma unroll
            for (int mt = 0; mt < 2; mt++) ldsm_x4(ah[mt], aBase + mt*(16*144) + kc2);
            #pragma unroll
            for (int np = 0; np < 4; np++) ldsm_x4(bb[np], bBase + np*(16*144) + kc2);
            #pragma unroll
            for (int mt = 0; mt < 2; mt++)
                #pragma unroll
                for (int np = 0; np < 4; np++) {
                    mma16816h(acc[mt][2*np],   ah[mt], &bb[np][0]);
                    mma16816h(acc[mt][2*np+1], ah[mt], &bb[np][2]);
                }
        }
        __syncthreads();   // protects buffer (s&1) from the s+2 prefetch
    }
    #undef G_LOAD

    #pragma unroll
    for (int mt = 0; mt < 2; mt++) {
        const int rg0 = bm*128 + wm*32 + mt*16 + l4;
        #pragma unroll
        for (int nt = 0; nt < 8; nt++) {
            const int cg = bn*128 + wn*64 + nt*8 + c2;
            if (MODE == 0) {
                float b0 = bias ? bias[cg] : 0.f;
                float b1 = bias ? bias[cg+1] : 0.f;
                float2 v0 = { acc[mt][nt][0] + b0, acc[mt][nt][1] + b1 };
                float2 v1 = { acc[mt][nt][2] + b0, acc[mt][nt][3] + b1 };
                *(float2*)(C + (size_t)rg0*Ncols + cg)     = v0;
                *(float2*)(C + (size_t)(rg0+8)*Ncols + cg) = v1;
            } else {
                if (bn < 8) {
                    *(uint32_t*)(CF + (size_t)rg0*INNER_ + cg) =
                        pack_f16x2(acc[mt][nt][0], acc[mt][nt][1]);
                    *(uint32_t*)(CF + (size_t)(rg0+8)*INNER_ + cg) =
                        pack_f16x2(acc[mt][nt][2], acc[mt][nt][3]);
                } else if (wn == 0) {
                    const int kcol = cg - 1024;
                    *(uint32_t*)(KF + (size_t)rg0*DHD + kcol) =
                        pack_f16x2(acc[mt][nt][0], acc[mt][nt][1]);
                    *(uint32_t*)(KF + (size_t)(rg0+8)*DHD + kcol) =
                        pack_f16x2(acc[mt][nt][2], acc[mt][nt][3]);
                } else {
                    const int d0 = cg - 1088;
                    const int bb_ = rg0 >> 11;
                    const int rl = rg0 & (SEQ - 1);
                    const size_t base = (size_t)(bb_*DHD + d0) * SEQ;
                    VTF[base + rl]           = __float2half_rn(acc[mt][nt][0]);
                    VTF[base + SEQ + rl]     = __float2half_rn(acc[mt][nt][1]);
                    VTF[base + rl + 8]       = __float2half_rn(acc[mt][nt][2]);
                    VTF[base + SEQ + rl + 8] = __float2half_rn(acc[mt][nt][3]);
                }
            }
        }
    }
}

// ---------------------------------------------------------------------------
// T5 relative-position bucket (mirrors jax fp32 math)
// ---------------------------------------------------------------------------
__device__ __forceinline__ int rel_bucket(int nn) {
    if (nn < 16) return nn;
    float t = logf((float)nn * (1.0f/16.0f)) / 2.0794415416798357f * 16.0f;
    int v = 16 + (int)t;
    return v < 31 ? v : 31;
}

// ---------------------------------------------------------------------------
// Flash attention v10: P via ex2.approx.f16x2; row-sum l via ones-column mma.
// 3-stage ring (3 real buffers, %3), ldmatrix, 2 CTAs/SM.
// ---------------------------------------------------------------------------
#define FSTRIDE 72                  // elements; 144 bytes/row
#define FTILE   (64*FSTRIDE*2)      // 9216 bytes per tile
#define FKFO 0
#define FVFO (1*FTILE)
#define FSTG (2*FTILE)              // 18432 per stage
#define FBIAS (3*FSTG)              // 55296
#define FLASH_SMEM (FBIAS + 2048*4) // 63488

__global__ __launch_bounds__(256, 2) void flash2(
    const __half* __restrict__ QF,
    const __half* __restrict__ KF, const __half* __restrict__ VTF,
    const float* __restrict__ rel_emb,
    __half* __restrict__ AOF)
{
    extern __shared__ __align__(16) char smem[];
    const uint32_t sb = s2u(smem);
    float* biasv = (float*)(smem + FBIAS);

    const int qtb = (SEQ/128 - 1) - blockIdx.x;
    const int h = blockIdx.y, b = blockIdx.z;
    const int tid = threadIdx.x, lane = tid & 31, w = tid >> 5;
    const int l4 = lane >> 2, c2 = (lane & 3) * 2;
    const int i0 = qtb * 128;
    const int wrow = i0 + w * 16;

    const uint32_t ltermB = ((lane & 7) + ((lane >> 4) << 3)) * (FSTRIDE*2)
                          + (((lane >> 3) & 1) << 4);

    for (int nn = tid; nn < 2048; nn += 256)
        biasv[nn] = rel_emb[rel_bucket(nn)*HEADS + h] * (8.0f * LOG2E);

    uint32_t qf[4][4];
    {
        const size_t rb = (size_t)(b*SEQ + wrow + l4) * INNER_ + h*DHD;
        #pragma unroll
        for (int k16 = 0; k16 < 4; k16++) {
            const int c = k16*16 + c2;
            qf[k16][0] = *(const uint32_t*)(QF + rb + c);
            qf[k16][1] = *(const uint32_t*)(QF + rb + 8*INNER_ + c);
            qf[k16][2] = *(const uint32_t*)(QF + rb + c + 8);
            qf[k16][3] = *(const uint32_t*)(QF + rb + 8*INNER_ + c + 8);
        }
    }

    float o[8][4];
    #pragma unroll
    for (int nt = 0; nt < 8; nt++)
        #pragma unroll
        for (int e = 0; e < 4; e++) o[nt][e] = 0.f;
    float lacc[4] = {0.f, 0.f, 0.f, 0.f};           // row sums via ones-mma
    float m0 = -INFINITY, m1 = -INFINITY;

    const uint32_t ones2 = 0x3C003C00u;             // fp16 {1,1}
    uint32_t onesb[2] = { ones2, ones2 };

    const int jmax = (i0 + 127) >> 6;
    const int iwmax = wrow + 15;

    #define LOADKV(JT, S) do { \
        const int _j0 = (JT) * 64; \
        const uint32_t _sb = sb + (uint32_t)(S) * FSTG; \
        _Pragma("unroll") \
        for (int q = 0; q < 2; q++) { \
            const int id = tid*2 + q; \
            const int r = id >> 3, cc = id & 7; \
            const uint32_t so = (uint32_t)(r*144 + cc*16); \
            const size_t ksrc = (size_t)(b*SEQ + _j0 + r)*DHD + cc*8; \
            cp16(_sb + FKFO + so, KF  + ksrc); \
            const size_t vsrc = (size_t)(b*DHD + r)*SEQ + _j0 + cc*8; \
            cp16(_sb + FVFO + so, VTF + vsrc); \
        } \
    } while (0)

    LOADKV(0, 0); cp_commit();
    LOADKV(1, 1); cp_commit();

    for (int jt = 0; jt <= jmax; jt++) {
        asm volatile("cp.async.wait_group 1;" ::: "memory");
        __syncthreads();
        if (jt + 2 <= jmax) LOADKV(jt + 2, (jt + 2) % 3);
        cp_commit();

        const int j0 = jt * 64;
        if (j0 <= iwmax) {
            const uint32_t stgb = sb + (uint32_t)(jt % 3) * FSTG;

            // ---- S = Q K^T ----
            float s[8][4];
            #pragma unroll
            for (int nt = 0; nt < 8; nt++)
                #pragma unroll
                for (int e = 0; e < 4; e++) s[nt][e] = 0.f;

            #pragma unroll
            for (int k16 = 0; k16 < 4; k16++) {
                const uint32_t kc2 = (uint32_t)k16 * 32;
                uint32_t kf4[4][4];
                #pragma unroll
                for (int np = 0; np < 4; np++)
                    ldsm_x4(kf4[np], stgb + FKFO + np*(16*144) + kc2 + ltermB);
                #pragma unroll
                for (int np = 0; np < 4; np++) {
                    mma16816h(s[2*np],   qf[k16], &kf4[np][0]);
                    mma16816h(s[2*np+1], qf[k16], &kf4[np][2]);
                }
            }

            // ---- bias (+ mask on diagonal tiles) ----
            const int irow0 = wrow + l4;
            if (j0 + 63 <= wrow) {
                #pragma unroll
                for (int nt = 0; nt < 8; nt++) {
                    #pragma unroll
                    for (int e = 0; e < 4; e++) {
                        const int ri = irow0 + ((e >> 1) << 3);
                        const int cj = j0 + nt*8 + c2 + (e & 1);
                        s[nt][e] += biasv[ri - cj];
                    }
                }
            } else {
                #pragma unroll
                for (int nt = 0; nt < 8; nt++) {
                    #pragma unroll
                    for (int e = 0; e < 4; e++) {
                        const int ri = irow0 + ((e >> 1) << 3);
                        const int cj = j0 + nt*8 + c2 + (e & 1);
                        const int nn = ri - cj;
                        if (nn < 0) s[nt][e] = -INFINITY;
                        else        s[nt][e] += biasv[nn];
                    }
                }
            }

            // ---- online max (warp-local) ----
            float mc0 = -INFINITY, mc1 = -INFINITY;
            #pragma unroll
            for (int nt = 0; nt < 8; nt++) {
                mc0 = fmaxf(mc0, fmaxf(s[nt][0], s[nt][1]));
                mc1 = fmaxf(mc1, fmaxf(s[nt][2], s[nt][3]));
            }
            mc0 = fmaxf(mc0, __shfl_xor_sync(0xffffffffu, mc0, 1));
            mc0 = fmaxf(mc0, __shfl_xor_sync(0xffffffffu, mc0, 2));
            mc1 = fmaxf(mc1, __shfl_xor_sync(0xffffffffu, mc1, 1));
            mc1 = fmaxf(mc1, __shfl_xor_sync(0xffffffffu, mc1, 2));
            const float mn0 = fmaxf(m0, mc0), mn1 = fmaxf(m1, mc1);
            const float sc0 = exp2f(m0 - mn0), sc1 = exp2f(m1 - mn1);
            m0 = mn0; m1 = mn1;

            #pragma unroll
            for (int nt = 0; nt < 8; nt++) {
                o[nt][0] *= sc0; o[nt][1] *= sc0;
                o[nt][2] *= sc1; o[nt][3] *= sc1;
            }
            lacc[0] *= sc0; lacc[1] *= sc0;
            lacc[2] *= sc1; lacc[3] *= sc1;

            // ---- P = exp2(s - m) fp16, O += P V, l += P·1 (tensor pipe) ----
            #pragma unroll
            for (int kk = 0; kk < 4; kk++) {
                uint32_t pf[4];
                pf[0] = ex2_f16x2(pack_f16x2(s[2*kk  ][0] - mn0, s[2*kk  ][1] - mn0));
                pf[1] = ex2_f16x2(pack_f16x2(s[2*kk  ][2] - mn1, s[2*kk  ][3] - mn1));
                pf[2] = ex2_f16x2(pack_f16x2(s[2*kk+1][0] - mn0, s[2*kk+1][1] - mn0));
                pf[3] = ex2_f16x2(pack_f16x2(s[2*kk+1][2] - mn1, s[2*kk+1][3] - mn1));
                mma16816h(lacc, pf, onesb);
                const uint32_t kc2 = (uint32_t)kk * 32;
                uint32_t vf[4][4];
                #pragma unroll
                for (int np = 0; np < 4; np++)
                    ldsm_x4(vf[np], stgb + FVFO + np*(16*144) + kc2 + ltermB);
                #pragma unroll
                for (int np = 0; np < 4; np++) {
                    mma16816h(o[2*np],   pf, &vf[np][0]);
                    mma16816h(o[2*np+1], pf, &vf[np][2]);
                }
            }
        }
    }
    #undef LOADKV

    // ---- normalize + write fp16 output ----
    {
        const float inv0 = 1.0f / lacc[0], inv1 = 1.0f / lacc[2];
        const size_t rb = (size_t)(b*SEQ + wrow + l4) * INNER_ + h*DHD;
        #pragma unroll
        for (int nt = 0; nt < 8; nt++) {
            const int col = nt*8 + c2;
            *(uint32_t*)(AOF + rb + col) =
                pack_f16x2(o[nt][0]*inv0, o[nt][1]*inv0);
            *(uint32_t*)(AOF + rb + 8*INNER_ + col) =
                pack_f16x2(o[nt][2]*inv1, o[nt][3]*inv1);
        }
    }
}

// ---------------------------------------------------------------------------
extern "C" void kernel_launch(void* const* d_in, const int* in_sizes, int n_in,
                              void* d_out, int out_size)
{
    const float* x       = (const float*)d_in[0];
    const float* Wq      = (const float*)d_in[1];
    const float* Wkv     = (const float*)d_in[2];
    const float* Wout    = (const float*)d_in[3];
    const float* bout    = (const float*)d_in[4];
    const float* rel_emb = (const float*)d_in[5];
    float* out = (float*)d_out;

    void* p;
    cudaGetSymbolAddress(&p, g_qf);   __half* qf  = (__half*)p;
    cudaGetSymbolAddress(&p, g_kf);   __half* kf  = (__half*)p;
    cudaGetSymbolAddress(&p, g_vtf);  __half* vtf = (__half*)p;
    cudaGetSymbolAddress(&p, g_aof);  __half* aof = (__half*)p;
    cudaGetSymbolAddress(&p, g_xf);   __half* xf  = (__half*)p;
    cudaGetSymbolAddress(&p, g_wcf);  __half* wcf = (__half*)p;
    cudaGetSymbolAddress(&p, g_wof);  __half* wof = (__half*)p;

    cudaFuncSetAttribute(gemm_mma<0>, cudaFuncAttributeMaxDynamicSharedMemorySize, GEMM_SMEM);
    cudaFuncSetAttribute(gemm_mma<1>, cudaFuncAttributeMaxDynamicSharedMemorySize, GEMM_SMEM);
    cudaFuncSetAttribute(flash2, cudaFuncAttributeMaxDynamicSharedMemorySize, FLASH_SMEM);

    dim3 tb(32, 8);
    transpose_wc_kernel<<<dim3((INNER_+2*DHD)/32, DIMM/32), tb>>>(Wq, Wkv, wcf);
    transpose_f16_kernel<<<dim3(DIMM/32, INNER_/32), tb>>>(Wout, wof, INNER_, DIMM, 1.0f);
    convert_f16_kernel<<<(ROWS*DIMM/4 + 255)/256, 256>>>(x, xf, ROWS*DIMM/4);

    gemm_mma<1><<<dim3(9, ROWS/128), 256, GEMM_SMEM>>>(xf, wcf,
                                                       nullptr, nullptr, 0,
                                                       qf, kf, vtf);
    flash2<<<dim3(SEQ/128, HEADS, BATCH), 256, FLASH_SMEM>>>(qf, kf, vtf,
                                                             rel_emb, aof);
    gemm_mma<0><<<dim3(DIMM/128, ROWS/128), 256, GEMM_SMEM>>>(aof, wof,
                                                              out, bout, DIMM,
                                                              nullptr, nullptr, nullptr);
}

// round 17
// speedup vs baseline: 1.7018x; 1.7018x over previous
#include <cuda_runtime.h>
#include <cuda_bf16.h>
#include <cuda_fp16.h>
#include <math.h>
#include <stdint.h>

#define BATCH 2
#define SEQ   2048
#define DIMM  1024
#define HEADS 16
#define DHD   64
#define INNER_ (HEADS*DHD)      // 1024
#define ROWS  (BATCH*SEQ)       // 4096
#define KDIM  1024
#define LOG2E 1.4426950408889634f

// ---------------- scratch (no cudaMalloc allowed) ----------------
__device__ __align__(256) __half g_qf [ROWS*INNER_];
__device__ __align__(256) __half g_kf [BATCH*SEQ*DHD];
__device__ __align__(256) __half g_vtf[BATCH*DHD*SEQ];
__device__ __align__(256) __half g_aof[ROWS*INNER_];
__device__ __align__(256) __half g_xf [ROWS*DIMM];
__device__ __align__(256) __half g_wcf[(INNER_+2*DHD)*DIMM];   // [Wq^T ; Wkv^T] fp16
__device__ __align__(256) __half g_wof[DIMM*INNER_];           // Wout^T fp16

// ---------------- helpers ----------------
__device__ __forceinline__ uint32_t s2u(const void* p) {
    uint32_t a;
    asm("{ .reg .u64 t; cvta.to.shared.u64 t, %1; cvt.u32.u64 %0, t; }"
        : "=r"(a) : "l"(p));
    return a;
}
__device__ __forceinline__ void cp16(uint32_t dst, const void* src) {
    asm volatile("cp.async.cg.shared.global [%0], [%1], 16;" :: "r"(dst), "l"(src));
}
__device__ __forceinline__ void cp_commit() { asm volatile("cp.async.commit_group;" ::: "memory"); }

__device__ __forceinline__ void mma16816h(float c[4], const uint32_t a[4], const uint32_t b[2]) {
    asm volatile("mma.sync.aligned.m16n8k16.row.col.f32.f16.f16.f32 "
        "{%0,%1,%2,%3}, {%4,%5,%6,%7}, {%8,%9}, {%0,%1,%2,%3};"
        : "+f"(c[0]), "+f"(c[1]), "+f"(c[2]), "+f"(c[3])
        : "r"(a[0]), "r"(a[1]), "r"(a[2]), "r"(a[3]), "r"(b[0]), "r"(b[1]));
}

// ldmatrix x4
__device__ __forceinline__ void ldsm_x4(uint32_t r[4], uint32_t saddr) {
    asm volatile("ldmatrix.sync.aligned.m8n8.x4.shared.b16 {%0,%1,%2,%3}, [%4];"
        : "=r"(r[0]), "=r"(r[1]), "=r"(r[2]), "=r"(r[3]) : "r"(saddr));
}

// pack two floats -> fp16x2 (first arg = low half)
__device__ __forceinline__ uint32_t pack_f16x2(float lo, float hi) {
    uint32_t r;
    asm("cvt.rn.f16x2.f32 %0, %1, %2;" : "=r"(r) : "f"(hi), "f"(lo));
    return r;
}
// exp2 on packed fp16x2
__device__ __forceinline__ uint32_t ex2_f16x2(uint32_t a) {
    uint32_t r;
    asm("ex2.approx.f16x2 %0, %1;" : "=r"(r) : "r"(a));
    return r;
}

// ---------------------------------------------------------------------------
// Prep kernels
// ---------------------------------------------------------------------------
__global__ __launch_bounds__(256) void convert_f16_kernel(
    const float* __restrict__ A, __half* __restrict__ F, int n4)
{
    int i = blockIdx.x * blockDim.x + threadIdx.x;
    if (i >= n4) return;
    float4 a = ((const float4*)A)[i];
    ((uint32_t*)F)[2*i]   = pack_f16x2(a.x, a.y);
    ((uint32_t*)F)[2*i+1] = pack_f16x2(a.z, a.w);
}

__global__ __launch_bounds__(256) void transpose_f16_kernel(
    const float* __restrict__ W, __half* __restrict__ T,
    int K, int N, float scale)
{
    __shared__ float tile[32][33];
    const int tx = threadIdx.x, ty = threadIdx.y;
    const int n0 = blockIdx.x * 32, k0 = blockIdx.y * 32;
    #pragma unroll
    for (int i = 0; i < 4; i++)
        tile[ty + 8*i][tx] = W[(size_t)(k0 + ty + 8*i) * N + n0 + tx];
    __syncthreads();
    #pragma unroll
    for (int i = 0; i < 4; i++) {
        float a = tile[tx][ty + 8*i] * scale;
        T[(size_t)(n0 + ty + 8*i) * K + k0 + tx] = __float2half_rn(a);
    }
}

__global__ __launch_bounds__(256) void transpose_wc_kernel(
    const float* __restrict__ Wq, const float* __restrict__ Wkv,
    __half* __restrict__ T)
{
    __shared__ float tile[32][33];
    const int tx = threadIdx.x, ty = threadIdx.y;
    const int n0 = blockIdx.x * 32, k0 = blockIdx.y * 32;
    const bool isq = (n0 < INNER_);
    const float* W = isq ? Wq : Wkv;
    const int N = isq ? INNER_ : 2*DHD;
    const int cb = isq ? n0 : n0 - INNER_;
    const float scale = isq ? 0.125f * LOG2E : 1.0f;
    #pragma unroll
    for (int i = 0; i < 4; i++)
        tile[ty + 8*i][tx] = W[(size_t)(k0 + ty + 8*i) * N + cb + tx];
    __syncthreads();
    #pragma unroll
    for (int i = 0; i < 4; i++) {
        float a = tile[tx][ty + 8*i] * scale;
        T[(size_t)(n0 + ty + 8*i) * KDIM + k0 + tx] = __float2half_rn(a);
    }
}

// ---------------------------------------------------------------------------
// HMMA GEMM fp16 (round-14 measured-good config): CTA 128x128, BK=32,
// 3-stage cp.async ring, one __syncthreads/stage, 2 CTAs/SM.
// MODE 0: fp32 C + bias.
// MODE 1: bn<8 -> fp16 q; bn==8 -> K fp16 (cols 0..63) + V^T fp16 (cols 64..127).
// ---------------------------------------------------------------------------
#define GBK 32
#define GNSTG (KDIM/GBK)            // 32
#define GSTRIDE 40                  // elements; 80 bytes/row
#define GMATB (128*GSTRIDE*2)       // 10240 bytes per matrix
#define GSTGB (2*GMATB)             // 20480 per stage
#define GEMM_SMEM (3*GSTGB)         // 61440 (3-stage ring)

template<int MODE>
__global__ __launch_bounds__(256, 2) void gemm_mma(
    const __half* __restrict__ Af, const __half* __restrict__ Bf,
    float* __restrict__ C, const float* __restrict__ bias, int Ncols,
    __half* __restrict__ CF, __half* __restrict__ KF, __half* __restrict__ VTF)
{
    extern __shared__ __align__(16) char smem[];
    const uint32_t sbuf = s2u(smem);
    const int tid = threadIdx.x, wid = tid >> 5, lane = tid & 31;
    const int l4 = lane >> 2, c2 = (lane & 3) * 2;
    const int wm = wid & 3, wn = wid >> 2;
    const int bn = blockIdx.x, bm = blockIdx.y;

    const uint32_t ltermB = ((lane & 7) + ((lane >> 4) << 3)) * (GSTRIDE*2)
                          + (((lane >> 3) & 1) << 4);
    const uint32_t ltermA = ((lane & 7) + (((lane >> 3) & 1) << 3)) * (GSTRIDE*2)
                          + (((lane >> 4) & 1) << 4);

    const __half* pA = Af + (size_t)(bm*128)*KDIM;
    const __half* pB = Bf + (size_t)(bn*128)*KDIM;

    const int r0 = tid >> 2, kc = tid & 3;
    const int r1 = r0 + 64;

    float acc[2][8][4];
    #pragma unroll
    for (int i = 0; i < 2; i++)
        #pragma unroll
        for (int j = 0; j < 8; j++)
            #pragma unroll
            for (int e = 0; e < 4; e++) acc[i][j][e] = 0.f;

    #define G_LOAD(S) do { \
        const int _k0 = (S) * GBK; \
        const uint32_t stb = sbuf + (uint32_t)((S) % 3) * GSTGB; \
        cp16(stb         + r0*80 + kc*16, pA + (size_t)r0*KDIM + _k0 + kc*8); \
        cp16(stb         + r1*80 + kc*16, pA + (size_t)r1*KDIM + _k0 + kc*8); \
        cp16(stb + GMATB + r0*80 + kc*16, pB + (size_t)r0*KDIM + _k0 + kc*8); \
        cp16(stb + GMATB + r1*80 + kc*16, pB + (size_t)r1*KDIM + _k0 + kc*8); \
    } while (0)

    G_LOAD(0); cp_commit();
    G_LOAD(1); cp_commit();

    for (int s = 0; s < GNSTG; s++) {
        asm volatile("cp.async.wait_group 1;" ::: "memory");
        __syncthreads();                       // stage s visible; stage s-1 buffer free
        if (s + 2 < GNSTG) G_LOAD(s + 2);
        cp_commit();                           // unconditional: keeps group counting

        const uint32_t stb = sbuf + (uint32_t)(s % 3) * GSTGB;
        const uint32_t aBase = stb         + (wm*32)*80 + ltermA;
        const uint32_t bBase = stb + GMATB + (wn*64)*80 + ltermB;

        #pragma unroll
        for (int k16 = 0; k16 < 2; k16++) {
            const uint32_t kc2 = (uint32_t)k16 * 32;
            uint32_t ah[2][4], bb[4][4];
            #pragma unroll
            for (int mt = 0; mt < 2; mt++) ldsm_x4(ah[mt], aBase + mt*(16*80) + kc2);
            #pragma unroll
            for (int np = 0; np < 4; np++) ldsm_x4(bb[np], bBase + np*(16*80) + kc2);
            #pragma unroll
            for (int mt = 0; mt < 2; mt++)
                #pragma unroll
                for (int np = 0; np < 4; np++) {
                    mma16816h(acc[mt][2*np],   ah[mt], &bb[np][0]);
                    mma16816h(acc[mt][2*np+1], ah[mt], &bb[np][2]);
                }
        }
    }
    #undef G_LOAD

    #pragma unroll
    for (int mt = 0; mt < 2; mt++) {
        const int rg0 = bm*128 + wm*32 + mt*16 + l4;
        #pragma unroll
        for (int nt = 0; nt < 8; nt++) {
            const int cg = bn*128 + wn*64 + nt*8 + c2;
            if (MODE == 0) {
                float b0 = bias ? bias[cg] : 0.f;
                float b1 = bias ? bias[cg+1] : 0.f;
                float2 v0 = { acc[mt][nt][0] + b0, acc[mt][nt][1] + b1 };
                float2 v1 = { acc[mt][nt][2] + b0, acc[mt][nt][3] + b1 };
                *(float2*)(C + (size_t)rg0*Ncols + cg)     = v0;
                *(float2*)(C + (size_t)(rg0+8)*Ncols + cg) = v1;
            } else {
                if (bn < 8) {
                    *(uint32_t*)(CF + (size_t)rg0*INNER_ + cg) =
                        pack_f16x2(acc[mt][nt][0], acc[mt][nt][1]);
                    *(uint32_t*)(CF + (size_t)(rg0+8)*INNER_ + cg) =
                        pack_f16x2(acc[mt][nt][2], acc[mt][nt][3]);
                } else if (wn == 0) {
                    const int kcol = cg - 1024;
                    *(uint32_t*)(KF + (size_t)rg0*DHD + kcol) =
                        pack_f16x2(acc[mt][nt][0], acc[mt][nt][1]);
                    *(uint32_t*)(KF + (size_t)(rg0+8)*DHD + kcol) =
                        pack_f16x2(acc[mt][nt][2], acc[mt][nt][3]);
                } else {
                    const int d0 = cg - 1088;
                    const int bb_ = rg0 >> 11;
                    const int rl = rg0 & (SEQ - 1);
                    const size_t base = (size_t)(bb_*DHD + d0) * SEQ;
                    VTF[base + rl]           = __float2half_rn(acc[mt][nt][0]);
                    VTF[base + SEQ + rl]     = __float2half_rn(acc[mt][nt][1]);
                    VTF[base + rl + 8]       = __float2half_rn(acc[mt][nt][2]);
                    VTF[base + SEQ + rl + 8] = __float2half_rn(acc[mt][nt][3]);
                }
            }
        }
    }
}

// ---------------------------------------------------------------------------
// T5 relative-position bucket (mirrors jax fp32 math)
// ---------------------------------------------------------------------------
__device__ __forceinline__ int rel_bucket(int nn) {
    if (nn < 16) return nn;
    float t = logf((float)nn * (1.0f/16.0f)) / 2.0794415416798357f * 16.0f;
    int v = 16 + (int)t;
    return v < 31 ? v : 31;
}

// ---------------------------------------------------------------------------
// Flash attention v10 (verified correct in round 16): P via ex2.approx.f16x2;
// row-sum l via ones-column mma. 3-stage ring, ldmatrix, 2 CTAs/SM.
// ---------------------------------------------------------------------------
#define FSTRIDE 72                  // elements; 144 bytes/row
#define FTILE   (64*FSTRIDE*2)      // 9216 bytes per tile
#define FKFO 0
#define FVFO (1*FTILE)
#define FSTG (2*FTILE)              // 18432 per stage
#define FBIAS (3*FSTG)              // 55296
#define FLASH_SMEM (FBIAS + 2048*4) // 63488

__global__ __launch_bounds__(256, 2) void flash2(
    const __half* __restrict__ QF,
    const __half* __restrict__ KF, const __half* __restrict__ VTF,
    const float* __restrict__ rel_emb,
    __half* __restrict__ AOF)
{
    extern __shared__ __align__(16) char smem[];
    const uint32_t sb = s2u(smem);
    float* biasv = (float*)(smem + FBIAS);

    const int qtb = (SEQ/128 - 1) - blockIdx.x;
    const int h = blockIdx.y, b = blockIdx.z;
    const int tid = threadIdx.x, lane = tid & 31, w = tid >> 5;
    const int l4 = lane >> 2, c2 = (lane & 3) * 2;
    const int i0 = qtb * 128;
    const int wrow = i0 + w * 16;

    const uint32_t ltermB = ((lane & 7) + ((lane >> 4) << 3)) * (FSTRIDE*2)
                          + (((lane >> 3) & 1) << 4);

    for (int nn = tid; nn < 2048; nn += 256)
        biasv[nn] = rel_emb[rel_bucket(nn)*HEADS + h] * (8.0f * LOG2E);

    uint32_t qf[4][4];
    {
        const size_t rb = (size_t)(b*SEQ + wrow + l4) * INNER_ + h*DHD;
        #pragma unroll
        for (int k16 = 0; k16 < 4; k16++) {
            const int c = k16*16 + c2;
            qf[k16][0] = *(const uint32_t*)(QF + rb + c);
            qf[k16][1] = *(const uint32_t*)(QF + rb + 8*INNER_ + c);
            qf[k16][2] = *(const uint32_t*)(QF + rb + c + 8);
            qf[k16][3] = *(const uint32_t*)(QF + rb + 8*INNER_ + c + 8);
        }
    }

    float o[8][4];
    #pragma unroll
    for (int nt = 0; nt < 8; nt++)
        #pragma unroll
        for (int e = 0; e < 4; e++) o[nt][e] = 0.f;
    float lacc[4] = {0.f, 0.f, 0.f, 0.f};           // row sums via ones-mma
    float m0 = -INFINITY, m1 = -INFINITY;

    const uint32_t ones2 = 0x3C003C00u;             // fp16 {1,1}
    uint32_t onesb[2] = { ones2, ones2 };

    const int jmax = (i0 + 127) >> 6;
    const int iwmax = wrow + 15;

    #define LOADKV(JT, S) do { \
        const int _j0 = (JT) * 64; \
        const uint32_t _sb = sb + (uint32_t)(S) * FSTG; \
        _Pragma("unroll") \
        for (int q = 0; q < 2; q++) { \
            const int id = tid*2 + q; \
            const int r = id >> 3, cc = id & 7; \
            const uint32_t so = (uint32_t)(r*144 + cc*16); \
            const size_t ksrc = (size_t)(b*SEQ + _j0 + r)*DHD + cc*8; \
            cp16(_sb + FKFO + so, KF  + ksrc); \
            const size_t vsrc = (size_t)(b*DHD + r)*SEQ + _j0 + cc*8; \
            cp16(_sb + FVFO + so, VTF + vsrc); \
        } \
    } while (0)

    LOADKV(0, 0); cp_commit();
    LOADKV(1, 1); cp_commit();

    for (int jt = 0; jt <= jmax; jt++) {
        asm volatile("cp.async.wait_group 1;" ::: "memory");
        __syncthreads();
        if (jt + 2 <= jmax) LOADKV(jt + 2, (jt + 2) % 3);
        cp_commit();

        const int j0 = jt * 64;
        if (j0 <= iwmax) {
            const uint32_t stgb = sb + (uint32_t)(jt % 3) * FSTG;

            // ---- S = Q K^T ----
            float s[8][4];
            #pragma unroll
            for (int nt = 0; nt < 8; nt++)
                #pragma unroll
                for (int e = 0; e < 4; e++) s[nt][e] = 0.f;

            #pragma unroll
            for (int k16 = 0; k16 < 4; k16++) {
                const uint32_t kc2 = (uint32_t)k16 * 32;
                uint32_t kf4[4][4];
                #pragma unroll
                for (int np = 0; np < 4; np++)
                    ldsm_x4(kf4[np], stgb + FKFO + np*(16*144) + kc2 + ltermB);
                #pragma unroll
                for (int np = 0; np < 4; np++) {
                    mma16816h(s[2*np],   qf[k16], &kf4[np][0]);
                    mma16816h(s[2*np+1], qf[k16], &kf4[np][2]);
                }
            }

            // ---- bias (+ mask on diagonal tiles) ----
            const int irow0 = wrow + l4;
            if (j0 + 63 <= wrow) {
                #pragma unroll
                for (int nt = 0; nt < 8; nt++) {
                    #pragma unroll
                    for (int e = 0; e < 4; e++) {
                        const int ri = irow0 + ((e >> 1) << 3);
                        const int cj = j0 + nt*8 + c2 + (e & 1);
                        s[nt][e] += biasv[ri - cj];
                    }
                }
            } else {
                #pragma unroll
                for (int nt = 0; nt < 8; nt++) {
                    #pragma unroll
                    for (int e = 0; e < 4; e++) {
                        const int ri = irow0 + ((e >> 1) << 3);
                        const int cj = j0 + nt*8 + c2 + (e & 1);
                        const int nn = ri - cj;
                        if (nn < 0) s[nt][e] = -INFINITY;
                        else        s[nt][e] += biasv[nn];
                    }
                }
            }

            // ---- online max (warp-local) ----
            float mc0 = -INFINITY, mc1 = -INFINITY;
            #pragma unroll
            for (int nt = 0; nt < 8; nt++) {
                mc0 = fmaxf(mc0, fmaxf(s[nt][0], s[nt][1]));
                mc1 = fmaxf(mc1, fmaxf(s[nt][2], s[nt][3]));
            }
            mc0 = fmaxf(mc0, __shfl_xor_sync(0xffffffffu, mc0, 1));
            mc0 = fmaxf(mc0, __shfl_xor_sync(0xffffffffu, mc0, 2));
            mc1 = fmaxf(mc1, __shfl_xor_sync(0xffffffffu, mc1, 1));
            mc1 = fmaxf(mc1, __shfl_xor_sync(0xffffffffu, mc1, 2));
            const float mn0 = fmaxf(m0, mc0), mn1 = fmaxf(m1, mc1);
            const float sc0 = exp2f(m0 - mn0), sc1 = exp2f(m1 - mn1);
            m0 = mn0; m1 = mn1;

            #pragma unroll
            for (int nt = 0; nt < 8; nt++) {
                o[nt][0] *= sc0; o[nt][1] *= sc0;
                o[nt][2] *= sc1; o[nt][3] *= sc1;
            }
            lacc[0] *= sc0; lacc[1] *= sc0;
            lacc[2] *= sc1; lacc[3] *= sc1;

            // ---- P = exp2(s - m) fp16, O += P V, l += P·1 (tensor pipe) ----
            #pragma unroll
            for (int kk = 0; kk < 4; kk++) {
                uint32_t pf[4];
                pf[0] = ex2_f16x2(pack_f16x2(s[2*kk  ][0] - mn0, s[2*kk  ][1] - mn0));
                pf[1] = ex2_f16x2(pack_f16x2(s[2*kk  ][2] - mn1, s[2*kk  ][3] - mn1));
                pf[2] = ex2_f16x2(pack_f16x2(s[2*kk+1][0] - mn0, s[2*kk+1][1] - mn0));
                pf[3] = ex2_f16x2(pack_f16x2(s[2*kk+1][2] - mn1, s[2*kk+1][3] - mn1));
                mma16816h(lacc, pf, onesb);
                const uint32_t kc2 = (uint32_t)kk * 32;
                uint32_t vf[4][4];
                #pragma unroll
                for (int np = 0; np < 4; np++)
                    ldsm_x4(vf[np], stgb + FVFO + np*(16*144) + kc2 + ltermB);
                #pragma unroll
                for (int np = 0; np < 4; np++) {
                    mma16816h(o[2*np],   pf, &vf[np][0]);
                    mma16816h(o[2*np+1], pf, &vf[np][2]);
                }
            }
        }
    }
    #undef LOADKV

    // ---- normalize + write fp16 output ----
    {
        const float inv0 = 1.0f / lacc[0], inv1 = 1.0f / lacc[2];
        const size_t rb = (size_t)(b*SEQ + wrow + l4) * INNER_ + h*DHD;
        #pragma unroll
        for (int nt = 0; nt < 8; nt++) {
            const int col = nt*8 + c2;
            *(uint32_t*)(AOF + rb + col) =
                pack_f16x2(o[nt][0]*inv0, o[nt][1]*inv0);
            *(uint32_t*)(AOF + rb + 8*INNER_ + col) =
                pack_f16x2(o[nt][2]*inv1, o[nt][3]*inv1);
        }
    }
}

// ---------------------------------------------------------------------------
extern "C" void kernel_launch(void* const* d_in, const int* in_sizes, int n_in,
                              void* d_out, int out_size)
{
    const float* x       = (const float*)d_in[0];
    const float* Wq      = (const float*)d_in[1];
    const float* Wkv     = (const float*)d_in[2];
    const float* Wout    = (const float*)d_in[3];
    const float* bout    = (const float*)d_in[4];
    const float* rel_emb = (const float*)d_in[5];
    float* out = (float*)d_out;

    void* p;
    cudaGetSymbolAddress(&p, g_qf);   __half* qf  = (__half*)p;
    cudaGetSymbolAddress(&p, g_kf);   __half* kf  = (__half*)p;
    cudaGetSymbolAddress(&p, g_vtf);  __half* vtf = (__half*)p;
    cudaGetSymbolAddress(&p, g_aof);  __half* aof = (__half*)p;
    cudaGetSymbolAddress(&p, g_xf);   __half* xf  = (__half*)p;
    cudaGetSymbolAddress(&p, g_wcf);  __half* wcf = (__half*)p;
    cudaGetSymbolAddress(&p, g_wof);  __half* wof = (__half*)p;

    cudaFuncSetAttribute(gemm_mma<0>, cudaFuncAttributeMaxDynamicSharedMemorySize, GEMM_SMEM);
    cudaFuncSetAttribute(gemm_mma<1>, cudaFuncAttributeMaxDynamicSharedMemorySize, GEMM_SMEM);
    cudaFuncSetAttribute(flash2, cudaFuncAttributeMaxDynamicSharedMemorySize, FLASH_SMEM);

    dim3 tb(32, 8);
    transpose_wc_kernel<<<dim3((INNER_+2*DHD)/32, DIMM/32), tb>>>(Wq, Wkv, wcf);
    transpose_f16_kernel<<<dim3(DIMM/32, INNER_/32), tb>>>(Wout, wof, INNER_, DIMM, 1.0f);
    convert_f16_kernel<<<(ROWS*DIMM/4 + 255)/256, 256>>>(x, xf, ROWS*DIMM/4);

    gemm_mma<1><<<dim3(9, ROWS/128), 256, GEMM_SMEM>>>(xf, wcf,
                                                       nullptr, nullptr, 0,
                                                       qf, kf, vtf);
    flash2<<<dim3(SEQ/128, HEADS, BATCH), 256, FLASH_SMEM>>>(qf, kf, vtf,
                                                             rel_emb, aof);
    gemm_mma<0><<<dim3(DIMM/128, ROWS/128), 256, GEMM_SMEM>>>(aof, wof,
                                                              out, bout, DIMM,
                                                              nullptr, nullptr, nullptr);
}